// round 3
// baseline (speedup 1.0000x reference)
#include <cuda_runtime.h>
#include <math.h>

#define NN      1536
#define FIN     1433
#define NH      64      // hidden = heads*hf
#define HEADS   8
#define HF      8
#define NC      7
#define MAXDEG  192
#define NEG_SLOPE 0.2f

// ---------------- scratch (device globals: no allocation allowed) ----------
__device__ float g_g1[NN * NH];      // x @ W1
__device__ float g_h1[NN * NH];      // elu(attention-1 output)
__device__ float g_g2[NN * NC];      // h1 @ W2
__device__ int   g_nbr[NN * MAXDEG]; // CSR neighbor indices per row
__device__ int   g_cnt[NN];          // degree per row
__device__ int   g_adj_is_u8;        // 1 if adjacency stored as 1-byte elems

// ---------------- K0: detect adjacency element width -----------------------
// Reads ONLY byte offsets < NN*NN (safe for any candidate dtype).
// For true 1-byte bool, every diagonal byte adj[i*NN+i] is nonzero.
// For int32 (1 -> bytes [1,0,0,0]) or float32 (1.0f -> [0,0,0x80,0x3f]) the
// diagonal byte position cycles (i mod 4), so the all-nonzero test fails.
__global__ void k_detect(const unsigned char* __restrict__ adj) {
    __shared__ int ok;
    if (threadIdx.x == 0) ok = 1;
    __syncthreads();
    for (int i = threadIdx.x; i < NN; i += blockDim.x) {
        if (adj[(size_t)i * NN + i] == 0) ok = 0;
    }
    __syncthreads();
    if (threadIdx.x == 0) g_adj_is_u8 = ok;
}

// ---------------- K1: adjacency (dense) -> CSR ------------------------------
// one warp per row; ballot-compact. 1536 = 48 chunks of 32.
__global__ void k_build_csr(const void* __restrict__ adjp) {
    int row  = blockIdx.x * 8 + (threadIdx.x >> 5);
    int lane = threadIdx.x & 31;
    int base = 0;
    if (g_adj_is_u8) {
        const unsigned char* r = (const unsigned char*)adjp + (size_t)row * NN;
        #pragma unroll 4
        for (int c0 = 0; c0 < NN; c0 += 32) {
            int c = c0 + lane;
            bool v = (r[c] != 0);
            unsigned b = __ballot_sync(0xffffffffu, v);
            if (v) {
                int pos = base + __popc(b & ((1u << lane) - 1u));
                if (pos < MAXDEG) g_nbr[row * MAXDEG + pos] = c;
            }
            base += __popc(b);
        }
    } else {
        const unsigned int* r = (const unsigned int*)adjp + (size_t)row * NN;
        #pragma unroll 4
        for (int c0 = 0; c0 < NN; c0 += 32) {
            int c = c0 + lane;
            bool v = (r[c] != 0u);   // nonzero word => true (int32 or f32 bool)
            unsigned b = __ballot_sync(0xffffffffu, v);
            if (v) {
                int pos = base + __popc(b & ((1u << lane) - 1u));
                if (pos < MAXDEG) g_nbr[row * MAXDEG + pos] = c;
            }
            base += __popc(b);
        }
    }
    if (lane == 0) g_cnt[row] = base < MAXDEG ? base : MAXDEG;
}

// ---------------- K2: GEMM1  g1 = x @ W1  (1536x1433 @ 1433x64) ------------
#define BM 8
#define BK 32
__global__ void k_gemm1(const float* __restrict__ x, const float* __restrict__ W1) {
    __shared__ float xs[BM][BK];
    __shared__ float ws[BK][NH];
    int block_row = blockIdx.x * BM;
    int tid = threadIdx.x;         // 0..255
    int j   = tid & 63;            // output col
    int rq  = tid >> 6;            // 0..3 (thread does rows rq and rq+4)
    float acc0 = 0.f, acc1 = 0.f;

    int lr = tid >> 5;             // 0..7  row for xs load
    int lk = tid & 31;             // 0..31 k for xs load

    for (int k0 = 0; k0 < FIN; k0 += BK) {
        int kk = k0 + lk;
        xs[lr][lk] = (kk < FIN) ? x[(size_t)(block_row + lr) * FIN + kk] : 0.f;
        #pragma unroll
        for (int t = tid; t < BK * NH; t += 256) {
            int wk = t >> 6, wj = t & 63;
            int kg = k0 + wk;
            ws[wk][wj] = (kg < FIN) ? W1[(size_t)kg * NH + wj] : 0.f;
        }
        __syncthreads();
        #pragma unroll
        for (int k = 0; k < BK; k++) {
            float w = ws[k][j];
            acc0 += xs[rq][k] * w;
            acc1 += xs[rq + 4][k] * w;
        }
        __syncthreads();
    }
    g_g1[(size_t)(block_row + rq)     * NH + j] = acc0;
    g_g1[(size_t)(block_row + rq + 4) * NH + j] = acc1;
}

// ---------------- K3: sparse GATv2 layer 1 + ELU ----------------------------
// one block of 64 threads per node. thread t = (head h = t/8, feat f = t%8).
__global__ void k_attn1(const float* __restrict__ a1v) {
    int i = blockIdx.x;
    int t = threadIdx.x;           // 0..63
    int h = t >> 3;
    int f = t & 7;

    __shared__ int   nb[MAXDEG];
    __shared__ float e_s[MAXDEG * HEADS];

    int cnt = g_cnt[i];
    for (int j = t; j < cnt; j += 64) nb[j] = g_nbr[i * MAXDEG + j];

    float gi = g_g1[(size_t)i * NH + t];
    float af = a1v[f];
    __syncthreads();

    // pass 1: scores e[j][h] = sum_f a1[f] * lrelu(gi + gj)
    for (int j = 0; j < cnt; j++) {
        float gj = g_g1[(size_t)nb[j] * NH + t];
        float s = gi + gj;
        s = (s > 0.f) ? s : NEG_SLOPE * s;
        float v = af * s;
        v += __shfl_down_sync(0xffffffffu, v, 4);
        v += __shfl_down_sync(0xffffffffu, v, 2);
        v += __shfl_down_sync(0xffffffffu, v, 1);
        if (f == 0) e_s[j * HEADS + h] = v;
    }
    __syncthreads();

    // pass 2: per-head softmax over neighbors + aggregation
    float m = -INFINITY;
    for (int j = 0; j < cnt; j++) m = fmaxf(m, e_s[j * HEADS + h]);
    float sum = 0.f;
    for (int j = 0; j < cnt; j++) sum += __expf(e_s[j * HEADS + h] - m);
    float inv = 1.f / sum;

    float acc = 0.f;
    for (int j = 0; j < cnt; j++) {
        float w = __expf(e_s[j * HEADS + h] - m);
        acc += w * g_g1[(size_t)nb[j] * NH + t];
    }
    acc *= inv;
    // fused ELU
    g_h1[(size_t)i * NH + t] = (acc > 0.f) ? acc : (__expf(acc) - 1.f);
}

// ---------------- K4: GEMM2  g2 = h1 @ W2  (1536x64 @ 64x7) ----------------
__global__ void k_gemm2(const float* __restrict__ W2) {
    int idx = blockIdx.x * blockDim.x + threadIdx.x;
    if (idx >= NN * NC) return;
    int i = idx / NC, c = idx - i * NC;
    float acc = 0.f;
    #pragma unroll
    for (int k = 0; k < NH; k++) acc += g_h1[(size_t)i * NH + k] * W2[k * NC + c];
    g_g2[idx] = acc;
}

// ---------------- K5: sparse GATv2 layer 2 (1 head, 7 feats) ---------------
// one warp per node, 4 nodes per 128-thread block.
__global__ void k_attn2(const float* __restrict__ a2v, float* __restrict__ out) {
    int warp = threadIdx.x >> 5;
    int lane = threadIdx.x & 31;
    int i = blockIdx.x * 4 + warp;
    if (i >= NN) return;

    int cnt = g_cnt[i];
    float a2r[NC], g2i[NC];
    #pragma unroll
    for (int c = 0; c < NC; c++) {
        a2r[c] = a2v[c];
        g2i[c] = g_g2[(size_t)i * NC + c];
    }

    const int QMAX = (MAXDEG + 31) / 32;   // 6
    int   njv[QMAX];
    float ev[QMAX];
    int nq = 0;
    float m = -INFINITY;
    for (int jj = lane; jj < cnt; jj += 32) {
        int nj = g_nbr[i * MAXDEG + jj];
        njv[nq] = nj;
        float e = 0.f;
        #pragma unroll
        for (int c = 0; c < NC; c++) {
            float s = g2i[c] + g_g2[(size_t)nj * NC + c];
            s = (s > 0.f) ? s : NEG_SLOPE * s;
            e += a2r[c] * s;
        }
        ev[nq++] = e;
        m = fmaxf(m, e);
    }
    #pragma unroll
    for (int o = 16; o > 0; o >>= 1) m = fmaxf(m, __shfl_xor_sync(0xffffffffu, m, o));

    float sum = 0.f;
    float acc[NC];
    #pragma unroll
    for (int c = 0; c < NC; c++) acc[c] = 0.f;
    for (int q = 0; q < nq; q++) {
        float w = __expf(ev[q] - m);
        sum += w;
        #pragma unroll
        for (int c = 0; c < NC; c++) acc[c] += w * g_g2[(size_t)njv[q] * NC + c];
    }
    #pragma unroll
    for (int o = 16; o > 0; o >>= 1) sum += __shfl_xor_sync(0xffffffffu, sum, o);
    float inv = 1.f / sum;

    #pragma unroll
    for (int c = 0; c < NC; c++) {
        float v = acc[c];
        #pragma unroll
        for (int o = 16; o > 0; o >>= 1) v += __shfl_xor_sync(0xffffffffu, v, o);
        if (lane == 0) out[(size_t)i * NC + c] = v * inv;
    }
}

// ---------------------------------------------------------------------------
extern "C" void kernel_launch(void* const* d_in, const int* in_sizes, int n_in,
                              void* d_out, int out_size) {
    const float* x   = (const float*)d_in[0];
    const void*  adj = (const void*)d_in[1];   // bool matrix; elem width detected on-device
    const float* W1  = (const float*)d_in[2];
    const float* a1  = (const float*)d_in[3];
    const float* W2  = (const float*)d_in[4];
    const float* a2  = (const float*)d_in[5];
    float*       out = (float*)d_out;

    k_detect<<<1, 512>>>((const unsigned char*)adj);
    k_build_csr<<<NN / 8, 256>>>(adj);
    k_gemm1<<<NN / BM, 256>>>(x, W1);
    k_attn1<<<NN, 64>>>(a1);
    k_gemm2<<<(NN * NC + 255) / 256, 256>>>(W2);
    k_attn2<<<(NN + 3) / 4, 128>>>(a2, out);
}

// round 4
// speedup vs baseline: 1.2405x; 1.2405x over previous
#include <cuda_runtime.h>
#include <math.h>
#include <stdint.h>

#define NN      1536
#define FIN     1433
#define NH      64      // hidden = heads*hf
#define HEADS   8
#define HF      8
#define NC      7
#define MAXDEG  64
#define NEG_SLOPE 0.2f

// ---------------- scratch (device globals: no allocation allowed) ----------
__device__ float g_p0[NN * NH];      // gemm1 K-half partials
__device__ float g_p1[NN * NH];
__device__ float g_g1[NN * NH];      // x @ W1
__device__ float g_g2[NN * NC];      // elu(attn1) @ W2
__device__ int   g_nbr[NN * MAXDEG]; // CSR neighbor indices per row
__device__ int   g_cnt[NN];          // degree per row
__device__ int   g_adj_is_u8;        // 1 if adjacency stored as 1-byte elems

// ---------------- K0: detect adjacency element width -----------------------
// For true 1-byte bool every diagonal byte adj[i*NN+i] is nonzero; for
// int32/float32-widened bool the diagonal byte position cycles (i mod 4),
// so the all-nonzero test fails. Reads only byte offsets < NN*NN.
__global__ void k_detect(const unsigned char* __restrict__ adj) {
    __shared__ int ok;
    if (threadIdx.x == 0) ok = 1;
    __syncthreads();
    for (int i = threadIdx.x; i < NN; i += blockDim.x)
        if (adj[(size_t)i * NN + i] == 0) ok = 0;
    __syncthreads();
    if (threadIdx.x == 0) g_adj_is_u8 = ok;
}

// ---------------- K1: adjacency (dense) -> CSR ------------------------------
// warp per row. All 48 ballot masks prefetched via unrolled independent
// loads (MLP ~48, one DRAM round trip), then register-resident compaction.
__global__ void k_build_csr(const void* __restrict__ adjp) {
    int row  = blockIdx.x * 8 + (threadIdx.x >> 5);
    int lane = threadIdx.x & 31;
    unsigned m[48];
    if (g_adj_is_u8) {
        const unsigned char* r = (const unsigned char*)adjp + (size_t)row * NN;
        #pragma unroll
        for (int q = 0; q < 48; q++)
            m[q] = __ballot_sync(0xffffffffu, r[q * 32 + lane] != 0);
    } else {
        const unsigned int* r = (const unsigned int*)adjp + (size_t)row * NN;
        #pragma unroll
        for (int q = 0; q < 48; q++)
            m[q] = __ballot_sync(0xffffffffu, r[q * 32 + lane] != 0u);
    }
    int base = 0;
    #pragma unroll
    for (int q = 0; q < 48; q++) {
        unsigned b = m[q];
        if (b & (1u << lane)) {
            int pos = base + __popc(b & ((1u << lane) - 1u));
            if (pos < MAXDEG) g_nbr[row * MAXDEG + pos] = q * 32 + lane;
        }
        base += __popc(b);
    }
    if (lane == 0) g_cnt[row] = base < MAXDEG ? base : MAXDEG;
}

// ---------------- K2: GEMM1 (K-split 2, packed f32x2 FMA) -------------------
// tile: 16 rows x 64 cols, 256 threads, each thread 1 row x 4 cols.
// blockIdx.x = row tile (96), blockIdx.y = K half (2).
#define GM 16
#define GBK 32
__global__ __launch_bounds__(256) void k_gemm1(const float* __restrict__ x,
                                               const float* __restrict__ W1) {
    __shared__ __align__(16) unsigned long long xs2[GM][GBK + 1]; // {x,x} packed
    __shared__ __align__(16) float ws[GBK][NH];

    int row0 = blockIdx.x * GM;
    int ky   = blockIdx.y;
    int kbeg = ky * 717;
    int kend = (ky == 0) ? 717 : FIN;

    int tid = threadIdx.x;
    int r   = tid >> 4;          // 0..15
    int cg  = tid & 15;          // colgroup of 4

    unsigned long long acc0 = 0ull, acc1 = 0ull;

    for (int k0 = kbeg; k0 < kend; k0 += GBK) {
        // load x tile, pre-packed {v,v}
        #pragma unroll
        for (int l = tid; l < GM * GBK; l += 256) {
            int rr = l >> 5, kk = l & 31;
            int kg = k0 + kk;
            float v = (kg < kend) ? x[(size_t)(row0 + rr) * FIN + kg] : 0.f;
            unsigned vu = __float_as_uint(v);
            unsigned long long p;
            asm("mov.b64 %0, {%1, %1};" : "=l"(p) : "r"(vu));
            xs2[rr][kk] = p;
        }
        // load W tile (float4)
        #pragma unroll
        for (int l = tid; l < GBK * 16; l += 256) {
            int kk = l >> 4, c4 = l & 15;
            int kg = k0 + kk;
            float4 w = (kg < kend) ? ((const float4*)(W1 + (size_t)kg * NH))[c4]
                                   : make_float4(0.f, 0.f, 0.f, 0.f);
            *((float4*)&ws[kk][c4 * 4]) = w;
        }
        __syncthreads();
        #pragma unroll
        for (int k = 0; k < GBK; k++) {
            unsigned long long xp = xs2[r][k];
            unsigned long long w0 = *(const unsigned long long*)&ws[k][cg * 4];
            unsigned long long w1 = *(const unsigned long long*)&ws[k][cg * 4 + 2];
            asm("fma.rn.f32x2 %0, %1, %2, %0;" : "+l"(acc0) : "l"(xp), "l"(w0));
            asm("fma.rn.f32x2 %0, %1, %2, %0;" : "+l"(acc1) : "l"(xp), "l"(w1));
        }
        __syncthreads();
    }
    float* dst = (ky == 0 ? g_p0 : g_p1) + (size_t)(row0 + r) * NH + cg * 4;
    unsigned a0l, a0h, a1l, a1h;
    asm("mov.b64 {%0, %1}, %2;" : "=r"(a0l), "=r"(a0h) : "l"(acc0));
    asm("mov.b64 {%0, %1}, %2;" : "=r"(a1l), "=r"(a1h) : "l"(acc1));
    dst[0] = __uint_as_float(a0l);
    dst[1] = __uint_as_float(a0h);
    dst[2] = __uint_as_float(a1l);
    dst[3] = __uint_as_float(a1h);
}

// ---------------- K3: sum K-half partials -----------------------------------
__global__ void k_sum() {
    int idx = blockIdx.x * blockDim.x + threadIdx.x;   // float4 index
    float4 a = ((const float4*)g_p0)[idx];
    float4 b = ((const float4*)g_p1)[idx];
    ((float4*)g_g1)[idx] = make_float4(a.x + b.x, a.y + b.y, a.z + b.z, a.w + b.w);
}

// ---------------- K4: sparse GATv2 layer 1 + ELU + GEMM2 fused --------------
// 2 nodes per 128-thread block. All neighbor rows cached in smem once.
__global__ __launch_bounds__(128) void k_attn1(const float* __restrict__ a1v,
                                               const float* __restrict__ W2) {
    __shared__ int   nb[2][MAXDEG];
    __shared__ float rows[2][MAXDEG][65];      // [node][j][feat], pad 65
    __shared__ float es[2][MAXDEG][HEADS];     // scores -> weights
    __shared__ float gis[2][64];
    __shared__ float ms[2][HEADS], ssum[2][HEADS];
    __shared__ float h1s[2][64];
    __shared__ float a1s[HF];
    __shared__ float w2s[NH * NC];

    int node = threadIdx.x >> 6;   // 0/1
    int t    = threadIdx.x & 63;
    int i    = blockIdx.x * 2 + node;
    int cnt  = g_cnt[i];

    if (threadIdx.x < HF) a1s[threadIdx.x] = a1v[threadIdx.x];
    for (int l = threadIdx.x; l < NH * NC; l += 128) w2s[l] = W2[l];
    if (t < cnt) nb[node][t] = g_nbr[i * MAXDEG + t];
    gis[node][t] = g_g1[(size_t)i * NH + t];
    __syncthreads();

    // cache neighbor rows (independent coalesced loads, MLP = cnt)
    for (int j = 0; j < cnt; j++)
        rows[node][j][t] = g_g1[(size_t)nb[node][j] * NH + t];
    __syncthreads();

    // scores: thread = (jl = t>>3, h = t&7); e[j][h] = sum_f a1[f]*lrelu(gi+gj)
    {
        int jl = t >> 3, h = t & 7;
        for (int j0 = 0; j0 < cnt; j0 += 8) {
            int j = j0 + jl;
            if (j < cnt) {
                float e = 0.f;
                #pragma unroll
                for (int f = 0; f < 8; f++) {
                    float s = gis[node][h * 8 + f] + rows[node][j][h * 8 + f];
                    s = (s > 0.f) ? s : NEG_SLOPE * s;
                    e += a1s[f] * s;
                }
                es[node][j][h] = e;
            }
        }
    }
    __syncthreads();

    // per-head softmax normalizers; es becomes weights
    if (t < HEADS) {
        int h = t;
        float m = -INFINITY;
        for (int j = 0; j < cnt; j++) m = fmaxf(m, es[node][j][h]);
        float s = 0.f;
        for (int j = 0; j < cnt; j++) {
            float w = __expf(es[node][j][h] - m);
            es[node][j][h] = w;
            s += w;
        }
        ssum[node][h] = s;
        ms[node][h] = m;
    }
    __syncthreads();

    // aggregate + ELU
    {
        int h = t >> 3;
        float acc = 0.f;
        for (int j = 0; j < cnt; j++)
            acc += es[node][j][h] * rows[node][j][t];
        acc /= ssum[node][h];
        h1s[node][t] = (acc > 0.f) ? acc : (__expf(acc) - 1.f);
    }
    __syncthreads();

    // fused GEMM2: g2[i,c] = sum_k h1[k] * W2[k,c]
    if (t < NC) {
        float acc = 0.f;
        #pragma unroll
        for (int k = 0; k < NH; k++) acc += h1s[node][k] * w2s[k * NC + t];
        g_g2[(size_t)i * NC + t] = acc;
    }
}

// ---------------- K5: sparse GATv2 layer 2 (1 head, 7 feats) ----------------
// one warp per node, 4 nodes per 128-thread block.
__global__ void k_attn2(const float* __restrict__ a2v, float* __restrict__ out) {
    int warp = threadIdx.x >> 5;
    int lane = threadIdx.x & 31;
    int i = blockIdx.x * 4 + warp;
    if (i >= NN) return;

    int cnt = g_cnt[i];
    float a2r[NC], g2i[NC];
    #pragma unroll
    for (int c = 0; c < NC; c++) {
        a2r[c] = a2v[c];
        g2i[c] = g_g2[(size_t)i * NC + c];
    }

    const int QMAX = (MAXDEG + 31) / 32;   // 2
    int   njv[QMAX];
    float ev[QMAX];
    int nq = 0;
    float m = -INFINITY;
    for (int jj = lane; jj < cnt; jj += 32) {
        int nj = g_nbr[i * MAXDEG + jj];
        njv[nq] = nj;
        float e = 0.f;
        #pragma unroll
        for (int c = 0; c < NC; c++) {
            float s = g2i[c] + g_g2[(size_t)nj * NC + c];
            s = (s > 0.f) ? s : NEG_SLOPE * s;
            e += a2r[c] * s;
        }
        ev[nq++] = e;
        m = fmaxf(m, e);
    }
    #pragma unroll
    for (int o = 16; o > 0; o >>= 1) m = fmaxf(m, __shfl_xor_sync(0xffffffffu, m, o));

    float sum = 0.f;
    float acc[NC];
    #pragma unroll
    for (int c = 0; c < NC; c++) acc[c] = 0.f;
    for (int q = 0; q < nq; q++) {
        float w = __expf(ev[q] - m);
        sum += w;
        #pragma unroll
        for (int c = 0; c < NC; c++) acc[c] += w * g_g2[(size_t)njv[q] * NC + c];
    }
    #pragma unroll
    for (int o = 16; o > 0; o >>= 1) sum += __shfl_xor_sync(0xffffffffu, sum, o);
    float inv = 1.f / sum;

    #pragma unroll
    for (int c = 0; c < NC; c++) {
        float v = acc[c];
        #pragma unroll
        for (int o = 16; o > 0; o >>= 1) v += __shfl_xor_sync(0xffffffffu, v, o);
        if (lane == 0) out[(size_t)i * NC + c] = v * inv;
    }
}

// ---------------------------------------------------------------------------
extern "C" void kernel_launch(void* const* d_in, const int* in_sizes, int n_in,
                              void* d_out, int out_size) {
    const float* x   = (const float*)d_in[0];
    const void*  adj = (const void*)d_in[1];   // bool matrix; width detected on-device
    const float* W1  = (const float*)d_in[2];
    const float* a1  = (const float*)d_in[3];
    const float* W2  = (const float*)d_in[4];
    const float* a2  = (const float*)d_in[5];
    float*       out = (float*)d_out;

    k_detect<<<1, 256>>>((const unsigned char*)adj);
    k_build_csr<<<NN / 8, 256>>>(adj);
    k_gemm1<<<dim3(NN / GM, 2), 256>>>(x, W1);
    k_sum<<<(NN * NH / 4) / 256, 256>>>();
    k_attn1<<<NN / 2, 128>>>(a1, W2);
    k_attn2<<<(NN + 3) / 4, 128>>>(a2, out);
}

// round 6
// speedup vs baseline: 1.4439x; 1.1640x over previous
#include <cuda_runtime.h>
#include <math.h>
#include <stdint.h>

#define NN      1536
#define FIN     1433
#define NH      64
#define HEADS   8
#define HF      8
#define NC      7
#define MAXDEG  64
#define NEG_SLOPE 0.2f
#define KSPLIT  4
#define KCH     360         // ceil-ish chunk; last = 1433-1080 = 353

// ---------------- scratch ---------------------------------------------------
__device__ float g_p[KSPLIT][NN * NH];   // gemm1 K-split partials
__device__ float g_g2[NN * NC];          // elu(attn1) @ W2
__device__ int   g_nbr[NN * MAXDEG];
__device__ int   g_cnt[NN];

// ---------------- K1: fused GEMM1 (192 blocks) + CSR build (384 blocks) -----
// blockIdx.x < 192 : gemm tile (tile = bx>>2, ksplit = bx&3), 32 rows x 64 cols
// blockIdx.x >= 192: csr block, 4 rows (warp per row), inline dtype probe
#define GM 32
#define GBK 32
__global__ __launch_bounds__(128) void k_main(const float* __restrict__ x,
                                              const float* __restrict__ W1,
                                              const unsigned char* __restrict__ adjb) {
    if (blockIdx.x < 192) {
        // ---------------- GEMM path ----------------
        __shared__ __align__(16) unsigned long long xs2[GM][GBK + 1]; // {v,v}
        __shared__ __align__(16) float ws[GBK][NH];

        int tile = blockIdx.x >> 2;
        int ks   = blockIdx.x & 3;
        int row0 = tile * GM;
        int kbeg = ks * KCH;
        int kend = (kbeg + KCH < FIN) ? (kbeg + KCH) : FIN;

        int tid = threadIdx.x;
        int r   = tid >> 3;          // 0..15 -> rows r, r+16
        int cg  = tid & 7;           // col group of 8 (4 f32x2 pairs)

        unsigned long long acc[2][4];
        #pragma unroll
        for (int a = 0; a < 2; a++)
            #pragma unroll
            for (int q = 0; q < 4; q++) acc[a][q] = 0ull;

        for (int k0 = kbeg; k0 < kend; k0 += GBK) {
            #pragma unroll
            for (int l = tid; l < GM * GBK; l += 128) {
                int rr = l >> 5, kk = l & 31;
                int kg = k0 + kk;
                float v = (kg < kend) ? x[(size_t)(row0 + rr) * FIN + kg] : 0.f;
                unsigned vu = __float_as_uint(v);
                unsigned long long p;
                asm("mov.b64 %0, {%1, %1};" : "=l"(p) : "r"(vu));
                xs2[rr][kk] = p;
            }
            #pragma unroll
            for (int l = tid; l < GBK * 16; l += 128) {
                int kk = l >> 4, c4 = l & 15;
                int kg = k0 + kk;
                float4 w = (kg < kend) ? ((const float4*)(W1 + (size_t)kg * NH))[c4]
                                       : make_float4(0.f, 0.f, 0.f, 0.f);
                *((float4*)&ws[kk][c4 * 4]) = w;
            }
            __syncthreads();
            #pragma unroll
            for (int k = 0; k < GBK; k++) {
                unsigned long long x0 = xs2[r][k];
                unsigned long long x1 = xs2[r + 16][k];
                const unsigned long long* wp = (const unsigned long long*)&ws[k][cg * 8];
                #pragma unroll
                for (int q = 0; q < 4; q++) {
                    unsigned long long wv = wp[q];
                    asm("fma.rn.f32x2 %0, %1, %2, %0;" : "+l"(acc[0][q]) : "l"(x0), "l"(wv));
                    asm("fma.rn.f32x2 %0, %1, %2, %0;" : "+l"(acc[1][q]) : "l"(x1), "l"(wv));
                }
            }
            __syncthreads();
        }
        #pragma unroll
        for (int a = 0; a < 2; a++) {
            unsigned long long* dst = (unsigned long long*)
                (g_p[ks] + (size_t)(row0 + r + a * 16) * NH + cg * 8);
            #pragma unroll
            for (int q = 0; q < 4; q++) dst[q] = acc[a][q];
        }
    } else {
        // ---------------- CSR path ----------------
        int cb   = blockIdx.x - 192;
        int row  = cb * 4 + (threadIdx.x >> 5);
        int lane = threadIdx.x & 31;
        // dtype probe: bytes at i*(NN+1), i=1..3 are diag self-loops for u8
        // (always nonzero) but land on bytes 1,2,3 of 4-byte elements for
        // widened bool (always zero for int32 0/1 and float32 0.0/1.0).
        bool isu8 = adjb[1 * (NN + 1)] && adjb[2 * (NN + 1)] && adjb[3 * (NN + 1)];
        unsigned m[48];
        if (isu8) {
            const unsigned char* rp = adjb + (size_t)row * NN;
            #pragma unroll
            for (int q = 0; q < 48; q++)
                m[q] = __ballot_sync(0xffffffffu, rp[q * 32 + lane] != 0);
        } else {
            const unsigned int* rp = (const unsigned int*)adjb + (size_t)row * NN;
            #pragma unroll
            for (int q = 0; q < 48; q++)
                m[q] = __ballot_sync(0xffffffffu, rp[q * 32 + lane] != 0u);
        }
        int base = 0;
        #pragma unroll
        for (int q = 0; q < 48; q++) {
            unsigned b = m[q];
            if (b & (1u << lane)) {
                int pos = base + __popc(b & ((1u << lane) - 1u));
                if (pos < MAXDEG) g_nbr[row * MAXDEG + pos] = q * 32 + lane;
            }
            base += __popc(b);
        }
        if (lane == 0) g_cnt[row] = base < MAXDEG ? base : MAXDEG;
    }
}

// ---------------- K2: attn layer1 + ELU + GEMM2 (partial-sum fused) ---------
__global__ __launch_bounds__(128) void k_attn1(const float* __restrict__ a1v,
                                               const float* __restrict__ W2) {
    __shared__ int   nb[2][MAXDEG];
    __shared__ float rows[2][MAXDEG][65];
    __shared__ float es[2][MAXDEG][HEADS];
    __shared__ float gis[2][64];
    __shared__ float ssum[2][HEADS];
    __shared__ float h1s[2][64];
    __shared__ float a1s[HF];
    __shared__ float w2s[NH * NC];

    int node = threadIdx.x >> 6;
    int t    = threadIdx.x & 63;
    int i    = blockIdx.x * 2 + node;
    int cnt  = g_cnt[i];

    if (threadIdx.x < HF) a1s[threadIdx.x] = a1v[threadIdx.x];
    for (int l = threadIdx.x; l < NH * NC; l += 128) w2s[l] = W2[l];
    if (t < cnt) nb[node][t] = g_nbr[i * MAXDEG + t];
    {
        size_t idx = (size_t)i * NH + t;
        gis[node][t] = g_p[0][idx] + g_p[1][idx] + g_p[2][idx] + g_p[3][idx];
    }
    __syncthreads();

    // cache neighbor rows, summing the 4 K-split partials (L2-resident)
    #pragma unroll 4
    for (int j = 0; j < cnt; j++) {
        size_t idx = (size_t)nb[node][j] * NH + t;
        rows[node][j][t] = g_p[0][idx] + g_p[1][idx] + g_p[2][idx] + g_p[3][idx];
    }
    __syncthreads();

    // scores e[j][h] = sum_f a1[f] * lrelu(gi[h,f] + gj[h,f])
    {
        int jl = t >> 3, h = t & 7;
        for (int j0 = 0; j0 < cnt; j0 += 8) {
            int j = j0 + jl;
            if (j < cnt) {
                float e = 0.f;
                #pragma unroll
                for (int f = 0; f < 8; f++) {
                    float s = gis[node][h * 8 + f] + rows[node][j][h * 8 + f];
                    s = (s > 0.f) ? s : NEG_SLOPE * s;
                    e += a1s[f] * s;
                }
                es[node][j][h] = e;
            }
        }
    }
    __syncthreads();

    // per-head softmax; es becomes unnormalized weights
    if (t < HEADS) {
        int h = t;
        float m = -INFINITY;
        for (int j = 0; j < cnt; j++) m = fmaxf(m, es[node][j][h]);
        float s = 0.f;
        for (int j = 0; j < cnt; j++) {
            float w = __expf(es[node][j][h] - m);
            es[node][j][h] = w;
            s += w;
        }
        ssum[node][h] = s;
    }
    __syncthreads();

    // aggregate + ELU
    {
        int h = t >> 3;
        float acc = 0.f;
        for (int j = 0; j < cnt; j++)
            acc += es[node][j][h] * rows[node][j][t];
        acc /= ssum[node][h];
        h1s[node][t] = (acc > 0.f) ? acc : (__expf(acc) - 1.f);
    }
    __syncthreads();

    // fused GEMM2
    if (t < NC) {
        float acc = 0.f;
        #pragma unroll
        for (int k = 0; k < NH; k++) acc += h1s[node][k] * w2s[k * NC + t];
        g_g2[(size_t)i * NC + t] = acc;
    }
}

// ---------------- K3: attn layer 2 (1 head, 7 feats) ------------------------
__global__ void k_attn2(const float* __restrict__ a2v, float* __restrict__ out) {
    int warp = threadIdx.x >> 5;
    int lane = threadIdx.x & 31;
    int i = blockIdx.x * 4 + warp;
    if (i >= NN) return;

    int cnt = g_cnt[i];
    float a2r[NC], g2i[NC];
    #pragma unroll
    for (int c = 0; c < NC; c++) {
        a2r[c] = a2v[c];
        g2i[c] = g_g2[(size_t)i * NC + c];
    }

    const int QMAX = (MAXDEG + 31) / 32;   // 2
    int   njv[QMAX];
    float ev[QMAX];
    int nq = 0;
    float m = -INFINITY;
    for (int jj = lane; jj < cnt; jj += 32) {
        int nj = g_nbr[i * MAXDEG + jj];
        njv[nq] = nj;
        float e = 0.f;
        #pragma unroll
        for (int c = 0; c < NC; c++) {
            float s = g2i[c] + g_g2[(size_t)nj * NC + c];
            s = (s > 0.f) ? s : NEG_SLOPE * s;
            e += a2r[c] * s;
        }
        ev[nq++] = e;
        m = fmaxf(m, e);
    }
    #pragma unroll
    for (int o = 16; o > 0; o >>= 1) m = fmaxf(m, __shfl_xor_sync(0xffffffffu, m, o));

    float sum = 0.f;
    float acc[NC];
    #pragma unroll
    for (int c = 0; c < NC; c++) acc[c] = 0.f;
    for (int q = 0; q < nq; q++) {
        float w = __expf(ev[q] - m);
        sum += w;
        #pragma unroll
        for (int c = 0; c < NC; c++) acc[c] += w * g_g2[(size_t)njv[q] * NC + c];
    }
    #pragma unroll
    for (int o = 16; o > 0; o >>= 1) sum += __shfl_xor_sync(0xffffffffu, sum, o);
    float inv = 1.f / sum;

    #pragma unroll
    for (int c = 0; c < NC; c++) {
        float v = acc[c];
        #pragma unroll
        for (int o = 16; o > 0; o >>= 1) v += __shfl_xor_sync(0xffffffffu, v, o);
        if (lane == 0) out[(size_t)i * NC + c] = v * inv;
    }
}

// ---------------------------------------------------------------------------
extern "C" void kernel_launch(void* const* d_in, const int* in_sizes, int n_in,
                              void* d_out, int out_size) {
    const float*         x   = (const float*)d_in[0];
    const unsigned char* adj = (const unsigned char*)d_in[1];
    const float*         W1  = (const float*)d_in[2];
    const float*         a1  = (const float*)d_in[3];
    const float*         W2  = (const float*)d_in[4];
    const float*         a2  = (const float*)d_in[5];
    float*               out = (float*)d_out;

    k_main <<<192 + 384, 128>>>(x, W1, adj);
    k_attn1<<<NN / 2, 128>>>(a1, W2);
    k_attn2<<<(NN + 3) / 4, 128>>>(a2, out);
}

// round 9
// speedup vs baseline: 1.9197x; 1.3295x over previous
#include <cuda_runtime.h>
#include <math.h>
#include <stdint.h>

#define NN      1536
#define FIN     1433
#define NH      64
#define HEADS   8
#define HF      8
#define NC      7
#define MAXDEG  64
#define NEG_SLOPE 0.2f

#define TILES   24          // 1536 / 64 rows
#define KSPLIT  16
#define KCH     90          // K per split (last covers 1433-1350=83, zero-padded)
#define KP      45          // k-pairs per split (odd -> conflict-free x strides)

// ---------------- scratch ---------------------------------------------------
__device__ float g_p[KSPLIT][NN * NH];   // gemm K-split partials
__device__ float g_g1[NN * NH];          // reduced x @ W1
__device__ float g_g2[NN * NC];          // elu(attn1) @ W2
__device__ int   g_nbr[NN * MAXDEG];
__device__ int   g_cnt[NN];
__device__ int   g_tick[TILES];          // reduction tickets (self-resetting)

// ---------------- K1: fused GEMM1 (384 blocks) + CSR (384 blocks) -----------
// gemm block: tile = bx>>4 (64 rows x 64 cols), ks = bx&15 (k-range of 90).
// Thread (128/blk): rg=tid>>3 -> rows rg*4..+3 ; cg=tid&7 -> cols cg*8..+7.
// k-paired f32x2: acc.lo accumulates even k, acc.hi odd k; combined at end.
__global__ __launch_bounds__(128) void k_main(const float* __restrict__ x,
                                              const float* __restrict__ W1,
                                              const unsigned char* __restrict__ adjb) {
    if (blockIdx.x < TILES * KSPLIT) {
        __shared__ unsigned long long xs[64 * KP];        // [row][pair]
        __shared__ unsigned long long ws[8 * KP * 8];     // [j][pair][cgrp]

        int tile = blockIdx.x >> 4;
        int ks   = blockIdx.x & 15;
        int row0 = tile * 64;
        int kbeg = ks * KCH;
        int kend = kbeg + KCH; if (kend > FIN) kend = FIN;
        int klen = kend - kbeg;
        int tid  = threadIdx.x;
        int rg   = tid >> 3;
        int cg   = tid & 7;

        // fill x: word (row*KCH + k); coalesced along k
        unsigned int* xsw = (unsigned int*)xs;
        for (int l = tid; l < 64 * KCH; l += 128) {
            int row = l / KCH, k = l - row * KCH;
            float v = (k < klen) ? x[(size_t)(row0 + row) * FIN + kbeg + k] : 0.f;
            xsw[row * KCH + k] = __float_as_uint(v);
        }
        // fill W transposed to [j][pair][cgrp] word layout
        unsigned int* wsw = (unsigned int*)ws;
        for (int l = tid; l < KCH * 64; l += 128) {
            int k = l >> 6, c = l & 63;
            float v = (k < klen) ? W1[(size_t)(kbeg + k) * NH + c] : 0.f;
            wsw[(c & 7) * (KP * 16) + (k >> 1) * 16 + ((c >> 3) << 1) + (k & 1)]
                = __float_as_uint(v);
        }
        __syncthreads();

        unsigned long long acc[4][8];
        #pragma unroll
        for (int i = 0; i < 4; i++)
            #pragma unroll
            for (int j = 0; j < 8; j++) acc[i][j] = 0ull;

        #pragma unroll 5
        for (int p = 0; p < KP; p++) {
            unsigned long long xv[4];
            #pragma unroll
            for (int i = 0; i < 4; i++) xv[i] = xs[(rg * 4 + i) * KP + p];
            #pragma unroll
            for (int j = 0; j < 8; j++) {
                unsigned long long wv = ws[j * (KP * 8) + p * 8 + cg];
                #pragma unroll
                for (int i = 0; i < 4; i++)
                    asm("fma.rn.f32x2 %0, %1, %2, %0;"
                        : "+l"(acc[i][j]) : "l"(xv[i]), "l"(wv));
            }
        }

        // combine even/odd partial sums, store this split's partial tile
        #pragma unroll
        for (int i = 0; i < 4; i++) {
            float* dst = g_p[ks] + (size_t)(row0 + rg * 4 + i) * NH + cg * 8;
            #pragma unroll
            for (int j = 0; j < 8; j += 2) {
                unsigned l0, h0, l1, h1;
                asm("mov.b64 {%0,%1}, %2;" : "=r"(l0), "=r"(h0) : "l"(acc[i][j]));
                asm("mov.b64 {%0,%1}, %2;" : "=r"(l1), "=r"(h1) : "l"(acc[i][j + 1]));
                float2 v = make_float2(__uint_as_float(l0) + __uint_as_float(h0),
                                       __uint_as_float(l1) + __uint_as_float(h1));
                *(float2*)(dst + j) = v;
            }
        }

        // last-arriving split block reduces the 16 partials for this tile
        __shared__ int s_last;
        __threadfence();
        __syncthreads();
        if (tid == 0) {
            int old = atomicAdd(&g_tick[tile], 1);
            s_last = (old == KSPLIT - 1);
        }
        __syncthreads();
        if (s_last) {
            for (int l = tid; l < 64 * 16; l += 128) {    // float4 units
                float4 s = make_float4(0.f, 0.f, 0.f, 0.f);
                #pragma unroll
                for (int q = 0; q < KSPLIT; q++) {
                    float4 v = *(const float4*)(g_p[q] + (size_t)row0 * NH + l * 4);
                    s.x += v.x; s.y += v.y; s.z += v.z; s.w += v.w;
                }
                *(float4*)(g_g1 + (size_t)row0 * NH + l * 4) = s;
            }
            if (tid == 0) g_tick[tile] = 0;   // reset for next graph replay
        }
    } else {
        // ---------------- CSR path ----------------
        int cb   = blockIdx.x - TILES * KSPLIT;
        int row  = cb * 4 + (threadIdx.x >> 5);
        int lane = threadIdx.x & 31;
        // dtype probe: bytes i*(NN+1), i=1..3 are diagonal self-loops for u8
        // (nonzero) but land on bytes 1..3 of 4-byte widened bool (zero).
        bool isu8 = adjb[1 * (NN + 1)] && adjb[2 * (NN + 1)] && adjb[3 * (NN + 1)];
        unsigned m[48];
        if (isu8) {
            const unsigned char* rp = adjb + (size_t)row * NN;
            #pragma unroll
            for (int q = 0; q < 48; q++)
                m[q] = __ballot_sync(0xffffffffu, rp[q * 32 + lane] != 0);
        } else {
            const unsigned int* rp = (const unsigned int*)adjb + (size_t)row * NN;
            #pragma unroll
            for (int q = 0; q < 48; q++)
                m[q] = __ballot_sync(0xffffffffu, rp[q * 32 + lane] != 0u);
        }
        int base = 0;
        #pragma unroll
        for (int q = 0; q < 48; q++) {
            unsigned b = m[q];
            if (b & (1u << lane)) {
                int pos = base + __popc(b & ((1u << lane) - 1u));
                if (pos < MAXDEG) g_nbr[row * MAXDEG + pos] = q * 32 + lane;
            }
            base += __popc(b);
        }
        if (lane == 0) g_cnt[row] = base < MAXDEG ? base : MAXDEG;
    }
}

// ---------------- K2: attn layer1 + ELU + GEMM2 fused ------------------------
__global__ __launch_bounds__(128) void k_attn1(const float* __restrict__ a1v,
                                               const float* __restrict__ W2) {
    __shared__ int   nb[2][MAXDEG];
    __shared__ float rows[2][MAXDEG][65];
    __shared__ float es[2][MAXDEG][HEADS];
    __shared__ float gis[2][64];
    __shared__ float ssum[2][HEADS];
    __shared__ float h1s[2][64];
    __shared__ float a1s[HF];
    __shared__ float w2s[NH * NC];

    int node = threadIdx.x >> 6;
    int t    = threadIdx.x & 63;
    int i    = blockIdx.x * 2 + node;
    int cnt  = g_cnt[i];

    if (threadIdx.x < HF) a1s[threadIdx.x] = a1v[threadIdx.x];
    for (int l = threadIdx.x; l < NH * NC; l += 128) w2s[l] = W2[l];
    if (t < cnt) nb[node][t] = g_nbr[i * MAXDEG + t];
    gis[node][t] = g_g1[(size_t)i * NH + t];
    __syncthreads();

    #pragma unroll 4
    for (int j = 0; j < cnt; j++)
        rows[node][j][t] = g_g1[(size_t)nb[node][j] * NH + t];
    __syncthreads();

    // scores e[j][h] = sum_f a1[f] * lrelu(gi[h,f] + gj[h,f])
    {
        int jl = t >> 3, h = t & 7;
        for (int j0 = 0; j0 < cnt; j0 += 8) {
            int j = j0 + jl;
            if (j < cnt) {
                float e = 0.f;
                #pragma unroll
                for (int f = 0; f < 8; f++) {
                    float s = gis[node][h * 8 + f] + rows[node][j][h * 8 + f];
                    s = (s > 0.f) ? s : NEG_SLOPE * s;
                    e += a1s[f] * s;
                }
                es[node][j][h] = e;
            }
        }
    }
    __syncthreads();

    if (t < HEADS) {
        int h = t;
        float m = -INFINITY;
        for (int j = 0; j < cnt; j++) m = fmaxf(m, es[node][j][h]);
        float s = 0.f;
        for (int j = 0; j < cnt; j++) {
            float w = __expf(es[node][j][h] - m);
            es[node][j][h] = w;
            s += w;
        }
        ssum[node][h] = s;
    }
    __syncthreads();

    {
        int h = t >> 3;
        float acc = 0.f;
        for (int j = 0; j < cnt; j++)
            acc += es[node][j][h] * rows[node][j][t];
        acc /= ssum[node][h];
        h1s[node][t] = (acc > 0.f) ? acc : (__expf(acc) - 1.f);
    }
    __syncthreads();

    if (t < NC) {
        float acc = 0.f;
        #pragma unroll
        for (int k = 0; k < NH; k++) acc += h1s[node][k] * w2s[k * NC + t];
        g_g2[(size_t)i * NC + t] = acc;
    }
}

// ---------------- K3: attn layer 2 (1 head, 7 feats) -------------------------
__global__ void k_attn2(const float* __restrict__ a2v, float* __restrict__ out) {
    int warp = threadIdx.x >> 5;
    int lane = threadIdx.x & 31;
    int i = blockIdx.x * 4 + warp;
    if (i >= NN) return;

    int cnt = g_cnt[i];
    float a2r[NC], g2i[NC];
    #pragma unroll
    for (int c = 0; c < NC; c++) {
        a2r[c] = a2v[c];
        g2i[c] = g_g2[(size_t)i * NC + c];
    }

    const int QMAX = (MAXDEG + 31) / 32;
    int   njv[QMAX];
    float ev[QMAX];
    int nq = 0;
    float m = -INFINITY;
    for (int jj = lane; jj < cnt; jj += 32) {
        int nj = g_nbr[i * MAXDEG + jj];
        njv[nq] = nj;
        float e = 0.f;
        #pragma unroll
        for (int c = 0; c < NC; c++) {
            float s = g2i[c] + g_g2[(size_t)nj * NC + c];
            s = (s > 0.f) ? s : NEG_SLOPE * s;
            e += a2r[c] * s;
        }
        ev[nq++] = e;
        m = fmaxf(m, e);
    }
    #pragma unroll
    for (int o = 16; o > 0; o >>= 1) m = fmaxf(m, __shfl_xor_sync(0xffffffffu, m, o));

    float sum = 0.f;
    float acc[NC];
    #pragma unroll
    for (int c = 0; c < NC; c++) acc[c] = 0.f;
    for (int q = 0; q < nq; q++) {
        float w = __expf(ev[q] - m);
        sum += w;
        #pragma unroll
        for (int c = 0; c < NC; c++) acc[c] += w * g_g2[(size_t)njv[q] * NC + c];
    }
    #pragma unroll
    for (int o = 16; o > 0; o >>= 1) sum += __shfl_xor_sync(0xffffffffu, sum, o);
    float inv = 1.f / sum;

    #pragma unroll
    for (int c = 0; c < NC; c++) {
        float v = acc[c];
        #pragma unroll
        for (int o = 16; o > 0; o >>= 1) v += __shfl_xor_sync(0xffffffffu, v, o);
        if (lane == 0) out[(size_t)i * NC + c] = v * inv;
    }
}

// ---------------------------------------------------------------------------
extern "C" void kernel_launch(void* const* d_in, const int* in_sizes, int n_in,
                              void* d_out, int out_size) {
    const float*         x   = (const float*)d_in[0];
    const unsigned char* adj = (const unsigned char*)d_in[1];
    const float*         W1  = (const float*)d_in[2];
    const float*         a1  = (const float*)d_in[3];
    const float*         W2  = (const float*)d_in[4];
    const float*         a2  = (const float*)d_in[5];
    float*               out = (float*)d_out;

    k_main <<<TILES * KSPLIT + NN / 4, 128>>>(x, W1, adj);
    k_attn1<<<NN / 2, 128>>>(a1, W2);
    k_attn2<<<(NN + 3) / 4, 128>>>(a2, out);
}

// round 10
// speedup vs baseline: 2.1958x; 1.1438x over previous
#include <cuda_runtime.h>
#include <math.h>
#include <stdint.h>

#define NN      1536
#define FIN     1433
#define NH      64
#define HEADS   8
#define HF      8
#define NC      7
#define MAXDEG  48
#define NEG_SLOPE 0.2f

#define TILES   24          // 1536 / 64 rows
#define KSPLIT  16
#define KCH     90          // K per split (last covers 83, zero-padded)
#define KP      45          // k-pairs per split

// ---------------- scratch ---------------------------------------------------
__device__ float g_p[KSPLIT][NN * NH];   // gemm K-split partials
__device__ float g_g1[NN * NH];          // reduced x @ W1
__device__ float g_g2[NN * NC];          // elu(attn1) @ W2
__device__ int   g_nbr[NN * MAXDEG];
__device__ int   g_cnt[NN];
__device__ int   g_tick[TILES];          // reduction tickets (self-resetting)
__device__ int   g_flag[NN];             // attn1->attn2 ready flags (reset in k_main)

// ---------------- K1: fused GEMM1 (384 blocks) + CSR (192 blocks) -----------
// gemm block (256 thr): tile = bx>>4 (64x64 rows/cols), ks = bx&15 (k-range 90)
//   thread: rg = tid>>3 -> rows rg*2, rg*2+1 ; cg = tid&7 -> cols cg*8..+7
//   k-paired f32x2: acc.lo = even-k partial, acc.hi = odd-k partial.
__global__ __launch_bounds__(256) void k_main(const float* __restrict__ x,
                                              const float* __restrict__ W1,
                                              const unsigned char* __restrict__ adjb) {
    if (blockIdx.x < TILES * KSPLIT) {
        __shared__ unsigned long long xs[64 * KP];        // [row][pair]
        __shared__ unsigned long long ws[8 * KP * 8];     // [j][pair][cgrp]

        int tile = blockIdx.x >> 4;
        int ks   = blockIdx.x & 15;
        int row0 = tile * 64;
        int kbeg = ks * KCH;
        int kend = kbeg + KCH; if (kend > FIN) kend = FIN;
        int klen = kend - kbeg;
        int tid  = threadIdx.x;
        int rg   = tid >> 3;
        int cg   = tid & 7;

        unsigned int* xsw = (unsigned int*)xs;
        for (int l = tid; l < 64 * KCH; l += 256) {
            int row = l / KCH, k = l - row * KCH;
            float v = (k < klen) ? x[(size_t)(row0 + row) * FIN + kbeg + k] : 0.f;
            xsw[row * KCH + k] = __float_as_uint(v);
        }
        unsigned int* wsw = (unsigned int*)ws;
        for (int l = tid; l < KCH * 64; l += 256) {
            int k = l >> 6, c = l & 63;
            float v = (k < klen) ? W1[(size_t)(kbeg + k) * NH + c] : 0.f;
            wsw[(c & 7) * (KP * 16) + (k >> 1) * 16 + ((c >> 3) << 1) + (k & 1)]
                = __float_as_uint(v);
        }
        __syncthreads();

        unsigned long long acc[2][8];
        #pragma unroll
        for (int i = 0; i < 2; i++)
            #pragma unroll
            for (int j = 0; j < 8; j++) acc[i][j] = 0ull;

        #pragma unroll 5
        for (int p = 0; p < KP; p++) {
            unsigned long long x0 = xs[(rg * 2 + 0) * KP + p];
            unsigned long long x1 = xs[(rg * 2 + 1) * KP + p];
            #pragma unroll
            for (int j = 0; j < 8; j++) {
                unsigned long long wv = ws[j * (KP * 8) + p * 8 + cg];
                asm("fma.rn.f32x2 %0, %1, %2, %0;" : "+l"(acc[0][j]) : "l"(x0), "l"(wv));
                asm("fma.rn.f32x2 %0, %1, %2, %0;" : "+l"(acc[1][j]) : "l"(x1), "l"(wv));
            }
        }

        #pragma unroll
        for (int i = 0; i < 2; i++) {
            float* dst = g_p[ks] + (size_t)(row0 + rg * 2 + i) * NH + cg * 8;
            #pragma unroll
            for (int j = 0; j < 8; j += 2) {
                unsigned l0, h0, l1, h1;
                asm("mov.b64 {%0,%1}, %2;" : "=r"(l0), "=r"(h0) : "l"(acc[i][j]));
                asm("mov.b64 {%0,%1}, %2;" : "=r"(l1), "=r"(h1) : "l"(acc[i][j + 1]));
                float2 v = make_float2(__uint_as_float(l0) + __uint_as_float(h0),
                                       __uint_as_float(l1) + __uint_as_float(h1));
                *(float2*)(dst + j) = v;
            }
        }

        // last-arriving split block reduces the 16 partials for this tile
        __shared__ int s_last;
        __threadfence();
        __syncthreads();
        if (tid == 0) {
            int old = atomicAdd(&g_tick[tile], 1);
            s_last = (old == KSPLIT - 1);
        }
        __syncthreads();
        if (s_last) {
            for (int l = tid; l < 64 * 16; l += 256) {    // float4 units
                float4 s = make_float4(0.f, 0.f, 0.f, 0.f);
                #pragma unroll
                for (int q = 0; q < KSPLIT; q++) {
                    float4 v = *(const float4*)(g_p[q] + (size_t)row0 * NH + l * 4);
                    s.x += v.x; s.y += v.y; s.z += v.z; s.w += v.w;
                }
                *(float4*)(g_g1 + (size_t)row0 * NH + l * 4) = s;
            }
            if (tid == 0) g_tick[tile] = 0;   // reset for next graph replay
        }
    } else {
        // ---------------- CSR path (8 rows/block, warp per row) ----------------
        int cb   = blockIdx.x - TILES * KSPLIT;
        int row  = cb * 8 + (threadIdx.x >> 5);
        int lane = threadIdx.x & 31;
        // dtype probe: bytes i*(NN+1), i=1..3 are diagonal self-loops for u8
        // (nonzero) but land on bytes 1..3 of 4-byte widened bool (zero).
        bool isu8 = adjb[1 * (NN + 1)] && adjb[2 * (NN + 1)] && adjb[3 * (NN + 1)];
        unsigned m[48];
        if (isu8) {
            const unsigned char* rp = adjb + (size_t)row * NN;
            #pragma unroll
            for (int q = 0; q < 48; q++)
                m[q] = __ballot_sync(0xffffffffu, rp[q * 32 + lane] != 0);
        } else {
            const unsigned int* rp = (const unsigned int*)adjb + (size_t)row * NN;
            #pragma unroll
            for (int q = 0; q < 48; q++)
                m[q] = __ballot_sync(0xffffffffu, rp[q * 32 + lane] != 0u);
        }
        int base = 0;
        #pragma unroll
        for (int q = 0; q < 48; q++) {
            unsigned b = m[q];
            if (b & (1u << lane)) {
                int pos = base + __popc(b & ((1u << lane) - 1u));
                if (pos < MAXDEG) g_nbr[row * MAXDEG + pos] = q * 32 + lane;
            }
            base += __popc(b);
        }
        if (lane == 0) {
            g_cnt[row]  = base < MAXDEG ? base : MAXDEG;
            g_flag[row] = 0;             // reset ready flag for this replay
        }
    }
}

// ---------------- K2: attn1 + ELU + GEMM2 + attn2 fused ---------------------
// 2 nodes per 128-thread block. After writing g_g2, block publishes a flag,
// then spins on its neighbors' flags and finishes layer 2 for its nodes.
// Deadlock-free: smem ~31KB -> 7 blocks/SM -> all 768 blocks co-resident.
__global__ __launch_bounds__(128) void k_attn(const float* __restrict__ a1v,
                                              const float* __restrict__ W2,
                                              const float* __restrict__ a2v,
                                              float* __restrict__ out) {
    __shared__ int   nb[2][MAXDEG];
    __shared__ float rows[2][MAXDEG][65];
    __shared__ float es[2][MAXDEG][HEADS];
    __shared__ float gis[2][64];
    __shared__ float ssum[2][HEADS];
    __shared__ float h1s[2][64];
    __shared__ float a1s[HF];
    __shared__ float a2s[NC];
    __shared__ float w2s[NH * NC];

    int node = threadIdx.x >> 6;
    int t    = threadIdx.x & 63;
    int i    = blockIdx.x * 2 + node;
    int cnt  = g_cnt[i];

    if (threadIdx.x < HF) a1s[threadIdx.x] = a1v[threadIdx.x];
    if (threadIdx.x >= 64 && threadIdx.x < 64 + NC) a2s[threadIdx.x - 64] = a2v[threadIdx.x - 64];
    for (int l = threadIdx.x; l < NH * NC; l += 128) w2s[l] = W2[l];
    if (t < cnt) nb[node][t] = g_nbr[i * MAXDEG + t];
    gis[node][t] = g_g1[(size_t)i * NH + t];
    __syncthreads();

    #pragma unroll 4
    for (int j = 0; j < cnt; j++)
        rows[node][j][t] = g_g1[(size_t)nb[node][j] * NH + t];
    __syncthreads();

    // scores e[j][h] = sum_f a1[f] * lrelu(gi[h,f] + gj[h,f])
    {
        int jl = t >> 3, h = t & 7;
        for (int j0 = 0; j0 < cnt; j0 += 8) {
            int j = j0 + jl;
            if (j < cnt) {
                float e = 0.f;
                #pragma unroll
                for (int f = 0; f < 8; f++) {
                    float s = gis[node][h * 8 + f] + rows[node][j][h * 8 + f];
                    s = (s > 0.f) ? s : NEG_SLOPE * s;
                    e += a1s[f] * s;
                }
                es[node][j][h] = e;
            }
        }
    }
    __syncthreads();

    if (t < HEADS) {
        int h = t;
        float m = -INFINITY;
        for (int j = 0; j < cnt; j++) m = fmaxf(m, es[node][j][h]);
        float s = 0.f;
        for (int j = 0; j < cnt; j++) {
            float w = __expf(es[node][j][h] - m);
            es[node][j][h] = w;
            s += w;
        }
        ssum[node][h] = s;
    }
    __syncthreads();

    {
        int h = t >> 3;
        float acc = 0.f;
        for (int j = 0; j < cnt; j++)
            acc += es[node][j][h] * rows[node][j][t];
        acc /= ssum[node][h];
        h1s[node][t] = (acc > 0.f) ? acc : (__expf(acc) - 1.f);
    }
    __syncthreads();

    // fused GEMM2 -> publish g_g2 row + ready flag
    if (t < NC) {
        float acc = 0.f;
        #pragma unroll
        for (int k = 0; k < NH; k++) acc += h1s[node][k] * w2s[k * NC + t];
        g_g2[(size_t)i * NC + t] = acc;
        __threadfence();
    }
    __syncthreads();
    if (t == 0) atomicExch(&g_flag[i], 1);

    // ---- phase 2: wait for neighbor g2 rows, then attention layer 2 ----
    for (int j = t; j < cnt; j += 64) {
        while (((volatile int*)g_flag)[nb[node][j]] == 0) { }
    }
    __syncthreads();
    __threadfence();

    if (t < 32) {   // warp 0 of each half handles its node
        int lane = t;
        float a2r[NC], g2i[NC];
        #pragma unroll
        for (int c = 0; c < NC; c++) {
            a2r[c] = a2s[c];
            g2i[c] = g_g2[(size_t)i * NC + c];
        }
        const int QMAX = (MAXDEG + 31) / 32;   // 2
        int   njv[QMAX];
        float ev[QMAX];
        int nq = 0;
        float m = -INFINITY;
        for (int jj = lane; jj < cnt; jj += 32) {
            int nj = nb[node][jj];
            njv[nq] = nj;
            float e = 0.f;
            #pragma unroll
            for (int c = 0; c < NC; c++) {
                float s = g2i[c] + g_g2[(size_t)nj * NC + c];
                s = (s > 0.f) ? s : NEG_SLOPE * s;
                e += a2r[c] * s;
            }
            ev[nq++] = e;
            m = fmaxf(m, e);
        }
        #pragma unroll
        for (int o = 16; o > 0; o >>= 1) m = fmaxf(m, __shfl_xor_sync(0xffffffffu, m, o));

        float sum = 0.f;
        float acc[NC];
        #pragma unroll
        for (int c = 0; c < NC; c++) acc[c] = 0.f;
        for (int q = 0; q < nq; q++) {
            float w = __expf(ev[q] - m);
            sum += w;
            #pragma unroll
            for (int c = 0; c < NC; c++) acc[c] += w * g_g2[(size_t)njv[q] * NC + c];
        }
        #pragma unroll
        for (int o = 16; o > 0; o >>= 1) sum += __shfl_xor_sync(0xffffffffu, sum, o);
        float inv = 1.f / sum;

        #pragma unroll
        for (int c = 0; c < NC; c++) {
            float v = acc[c];
            #pragma unroll
            for (int o = 16; o > 0; o >>= 1) v += __shfl_xor_sync(0xffffffffu, v, o);
            if (lane == 0) out[(size_t)i * NC + c] = v * inv;
        }
    }
}

// ---------------------------------------------------------------------------
extern "C" void kernel_launch(void* const* d_in, const int* in_sizes, int n_in,
                              void* d_out, int out_size) {
    const float*         x   = (const float*)d_in[0];
    const unsigned char* adj = (const unsigned char*)d_in[1];
    const float*         W1  = (const float*)d_in[2];
    const float*         a1  = (const float*)d_in[3];
    const float*         W2  = (const float*)d_in[4];
    const float*         a2  = (const float*)d_in[5];
    float*               out = (float*)d_out;

    k_main<<<TILES * KSPLIT + NN / 8, 256>>>(x, W1, adj);
    k_attn<<<NN / 2, 128>>>(a1, W2, a2, out);
}